// round 2
// baseline (speedup 1.0000x reference)
#include <cuda_runtime.h>
#include <math.h>

#define BB 4
#define TT 8192
#define NV 64
#define FF 16
#define CC 1024   // NV*FF
#define OO 32

// ---------------- scratch (static device globals; no allocation) -------------
__device__ __align__(16) float g_lhs[BB*NV*FF];      // lhs_pre[b,n,f]
__device__ __align__(16) float g_R2 [BB*NV*FF];      // R2[b,n,f]
__device__ __align__(16) float g_S  [BB*NV*NV];      // softmaxed S[b,n,k]
__device__ __align__(16) float g_Weff[BB*3*CC*OO];   // Weff[b][k][c][o]

// ---------------- kernel 0: zero accumulators --------------------------------
__global__ void k_zero() {
    int i = blockIdx.x*blockDim.x + threadIdx.x;
    if (i < BB*NV*FF) { g_lhs[i] = 0.f; g_R2[i] = 0.f; }
}

// ---------------- kernel 1: streaming reductions over T -----------------------
// grid (T/128, B), block 256. Thread j owns channels c = 4j..4j+3
// (n = j>>2, f0 = 4*(j&3)). Per row t: one float4 load, warp-local 4-lane
// reduction for s3 = sum_f W3[f]*x, then accumulate lhs_pre and R2.
__global__ void __launch_bounds__(256) k1_reduce(
    const float* __restrict__ x, const float* __restrict__ W1,
    const float* __restrict__ W2, const float* __restrict__ W3)
{
    const int b  = blockIdx.y;
    const int t0 = blockIdx.x * 128;
    const int j  = threadIdx.x;
    const int n  = j >> 2;
    const int f0 = (j & 3) * 4;

    __shared__ __align__(16) float sW1[128];
    __shared__ __align__(16) float sW2[16][129];

    if (j < 128) sW1[j] = W1[t0 + j];
    for (int idx = j; idx < 16*128; idx += 256) {
        int f = idx >> 7, tt = idx & 127;
        sW2[f][tt] = W2[f*TT + t0 + tt];
    }
    float w3v[4];
    #pragma unroll
    for (int d = 0; d < 4; d++) w3v[d] = W3[f0 + d];
    __syncthreads();

    float lhsacc[4] = {0,0,0,0};
    float r2acc[4]  = {0,0,0,0};
    const float4* xr = reinterpret_cast<const float4*>(
        x + (size_t)b*TT*CC + (size_t)t0*CC) + j;

    for (int tt = 0; tt < 128; tt++) {
        float4 xv = xr[(size_t)tt*256];
        float s3 = xv.x*w3v[0] + xv.y*w3v[1] + xv.z*w3v[2] + xv.w*w3v[3];
        s3 += __shfl_xor_sync(0xffffffffu, s3, 1);
        s3 += __shfl_xor_sync(0xffffffffu, s3, 2);
        float w1 = sW1[tt];
        lhsacc[0] += w1*xv.x; lhsacc[1] += w1*xv.y;
        lhsacc[2] += w1*xv.z; lhsacc[3] += w1*xv.w;
        #pragma unroll
        for (int d = 0; d < 4; d++) r2acc[d] += sW2[f0+d][tt] * s3;
    }
    #pragma unroll
    for (int d = 0; d < 4; d++) {
        atomicAdd(&g_lhs[(b*NV + n)*FF + f0 + d], lhsacc[d]);
        atomicAdd(&g_R2 [(b*NV + n)*FF + f0 + d], r2acc[d]);
    }
}

// ---------------- kernel 2a: attention matrix S -------------------------------
// grid B, block 256.
__global__ void __launch_bounds__(256) k2a_S(
    const float* __restrict__ bs, const float* __restrict__ Vs)
{
    const int b = blockIdx.x;
    const int tid = threadIdx.x;
    __shared__ __align__(16) float lhs_s[NV*FF];
    __shared__ __align__(16) float R2_s [NV*FF];
    __shared__ __align__(16) float P_s  [NV*NV];
    __shared__ __align__(16) float S0_s [NV*NV];

    for (int i = tid; i < NV*FF; i += 256) {
        lhs_s[i] = g_lhs[b*NV*FF + i];
        R2_s[i]  = g_R2 [b*NV*FF + i];
    }
    __syncthreads();

    // P[m,k] = sigmoid(product[b,m,k] + bs[m,k]),
    // product[b,m,k] = sum_f lhs_pre[b,m,f]*R2[b,k,f]
    for (int i = tid; i < NV*NV; i += 256) {
        int m = i >> 6, k = i & 63;
        float acc = 0.f;
        #pragma unroll
        for (int f = 0; f < FF; f++) acc += lhs_s[m*FF+f] * R2_s[k*FF+f];
        acc += bs[i];
        P_s[i] = 1.f / (1.f + expf(-acc));
    }
    __syncthreads();

    // S0[n,k] = sum_m Vs[n,m] * P[m,k]
    for (int i = tid; i < NV*NV; i += 256) {
        int nn = i >> 6, k = i & 63;
        float acc = 0.f;
        #pragma unroll 8
        for (int m = 0; m < NV; m++) acc += Vs[nn*NV+m] * P_s[m*NV+k];
        S0_s[i] = acc;
    }
    __syncthreads();

    // softmax over n (rows) for each column k
    if (tid < NV) {
        const int k = tid;
        float mx = -1e30f;
        for (int nn = 0; nn < NV; nn++) mx = fmaxf(mx, S0_s[nn*NV+k]);
        float sum = 0.f;
        for (int nn = 0; nn < NV; nn++) sum += expf(S0_s[nn*NV+k] - mx);
        float inv = 1.f / sum;
        for (int nn = 0; nn < NV; nn++)
            g_S[b*NV*NV + nn*NV + k] = expf(S0_s[nn*NV+k] - mx) * inv;
    }
}

// ---------------- kernel 2b: effective conv weights ---------------------------
// grid (O, B), block 256.
// Weff[b,o,m*F+f,k] = sum_n S[b,m,n]*adj[n,n]*conv_w[o,n*F+f,k]
__global__ void __launch_bounds__(256) k2b_weff(
    const float* __restrict__ adj, const float* __restrict__ conv_w)
{
    const int o = blockIdx.x, b = blockIdx.y;
    const int tid = threadIdx.x;
    __shared__ __align__(16) float Sd[NV*NV];     // S[b,m,n]*dadj[n]
    __shared__ __align__(16) float cw[CC*3];      // conv_w[o,:,:]

    for (int i = tid; i < NV*NV; i += 256) {
        int nn = i & 63;
        Sd[i] = g_S[b*NV*NV + i] * adj[nn*NV + nn];
    }
    for (int i = tid; i < CC*3; i += 256)
        cw[i] = conv_w[(size_t)o*CC*3 + i];
    __syncthreads();

    for (int i = tid; i < CC*3; i += 256) {
        int c = i / 3, k = i - c*3;
        int m = c >> 4, f = c & 15;
        float acc = 0.f;
        #pragma unroll 8
        for (int nn = 0; nn < NV; nn++)
            acc += Sd[m*NV+nn] * cw[(nn*FF+f)*3 + k];
        g_Weff[(((size_t)b*3 + k)*CC + c)*OO + o] = acc;
    }
}

// ---------------- kernel 3: conv1d(x, Weff_b) ---------------------------------
// out[b,t,o] = sum_k sum_c x[b,t+k-1,c] * Weff[b,k,c,o]
// grid (T/128, B), block 128. Thread (tx=o-quad, ty=t-octet) computes 8t x 4o.
#define K3TT 128
#define K3CH 32
#define XS_STRIDE 33

__global__ void __launch_bounds__(128) k3_conv(
    const float* __restrict__ x, float* __restrict__ out)
{
    const int b    = blockIdx.y;
    const int tblk = blockIdx.x * K3TT;
    const int tid  = threadIdx.x;
    const int tx   = tid & 7;    // o = 4*tx .. 4*tx+3
    const int ty   = tid >> 3;   // t rows ty*8 .. ty*8+7

    __shared__ __align__(16) float xs[(K3TT+2)*XS_STRIDE];   // t = tblk-1 .. +128
    __shared__ __align__(16) float ws[3*K3CH*OO];            // [k][cc][o]

    float acc[8][4];
    #pragma unroll
    for (int r = 0; r < 8; r++)
        #pragma unroll
        for (int d = 0; d < 4; d++) acc[r][d] = 0.f;

    const float* xb = x + (size_t)b*TT*CC;
    const float* wb = g_Weff + (size_t)b*3*CC*OO;

    for (int c0 = 0; c0 < CC; c0 += K3CH) {
        __syncthreads();
        // stage x tile: 130 rows x 32 cols (scalar stores into padded smem)
        for (int idx = tid; idx < (K3TT+2)*(K3CH/4); idx += 128) {
            int row = idx >> 3;            // /(K3CH/4)
            int q   = idx & 7;
            int tg  = tblk - 1 + row;
            float4 v = make_float4(0.f,0.f,0.f,0.f);
            if (tg >= 0 && tg < TT)
                v = *reinterpret_cast<const float4*>(xb + (size_t)tg*CC + c0 + q*4);
            float* dst = &xs[row*XS_STRIDE + q*4];
            dst[0]=v.x; dst[1]=v.y; dst[2]=v.z; dst[3]=v.w;
        }
        // stage weights: 3 x 32 x 32
        for (int idx = tid; idx < 3*K3CH*OO/4; idx += 128) {
            int e = idx * 4;
            int k = e / (K3CH*OO);
            int rem = e - k*K3CH*OO;
            float4 v = *reinterpret_cast<const float4*>(
                wb + (size_t)k*CC*OO + (size_t)c0*OO + rem);
            *reinterpret_cast<float4*>(ws + e) = v;
        }
        __syncthreads();

        for (int cc = 0; cc < K3CH; cc++) {
            float xv[10];
            #pragma unroll
            for (int rr = 0; rr < 10; rr++)
                xv[rr] = xs[(ty*8 + rr)*XS_STRIDE + cc];
            float4 w0 = *reinterpret_cast<const float4*>(ws + (0*K3CH+cc)*OO + tx*4);
            float4 w1 = *reinterpret_cast<const float4*>(ws + (1*K3CH+cc)*OO + tx*4);
            float4 w2 = *reinterpret_cast<const float4*>(ws + (2*K3CH+cc)*OO + tx*4);
            #pragma unroll
            for (int r = 0; r < 8; r++) {
                acc[r][0] += xv[r]*w0.x + xv[r+1]*w1.x + xv[r+2]*w2.x;
                acc[r][1] += xv[r]*w0.y + xv[r+1]*w1.y + xv[r+2]*w2.y;
                acc[r][2] += xv[r]*w0.z + xv[r+1]*w1.z + xv[r+2]*w2.z;
                acc[r][3] += xv[r]*w0.w + xv[r+1]*w1.w + xv[r+2]*w2.w;
            }
        }
    }

    float* ob = out + (size_t)b*TT*OO;
    #pragma unroll
    for (int r = 0; r < 8; r++) {
        int t = tblk + ty*8 + r;
        float4 v = make_float4(acc[r][0], acc[r][1], acc[r][2], acc[r][3]);
        *reinterpret_cast<float4*>(ob + (size_t)t*OO + tx*4) = v;
    }
}

// ---------------- launch ------------------------------------------------------
extern "C" void kernel_launch(void* const* d_in, const int* in_sizes, int n_in,
                              void* d_out, int out_size)
{
    const float* x      = (const float*)d_in[0];
    const float* adj    = (const float*)d_in[1];
    const float* W1     = (const float*)d_in[2];
    const float* W2     = (const float*)d_in[3];
    const float* W3     = (const float*)d_in[4];
    const float* bs     = (const float*)d_in[5];
    const float* Vs     = (const float*)d_in[6];
    const float* conv_w = (const float*)d_in[7];
    float* out = (float*)d_out;

    k_zero<<<16, 256>>>();
    k1_reduce<<<dim3(TT/128, BB), 256>>>(x, W1, W2, W3);
    k2a_S<<<BB, 256>>>(bs, Vs);
    k2b_weff<<<dim3(OO, BB), 256>>>(adj, conv_w);
    k3_conv<<<dim3(TT/K3TT, BB), 128>>>(x, out);
}

// round 3
// speedup vs baseline: 1.0966x; 1.0966x over previous
#include <cuda_runtime.h>
#include <math.h>

#define BB 4
#define TT 8192
#define NV 64
#define FF 16
#define CC 1024   // NV*FF
#define OO 32

// ---------------- scratch (static device globals; no allocation) -------------
__device__ __align__(16) float g_lhs[BB*NV*FF];      // lhs_pre[b,n,f]
__device__ __align__(16) float g_R2 [BB*NV*FF];      // R2[b,n,f]
__device__ __align__(16) float g_S  [BB*NV*NV];      // softmaxed S[b,n,k]
__device__ __align__(16) float g_Weff[BB*3*CC*OO];   // Weff[b][k][c][o]

// ---------------- packed f32x2 helpers ---------------------------------------
__device__ __forceinline__ void ffma2(unsigned long long& d,
                                      unsigned long long a,
                                      unsigned long long b) {
    asm("fma.rn.f32x2 %0, %1, %2, %0;" : "+l"(d) : "l"(a), "l"(b));
}
__device__ __forceinline__ unsigned long long splat2(float v) {
    unsigned long long r;
    asm("mov.b64 %0, {%1, %1};" : "=l"(r) : "f"(v));
    return r;
}
__device__ __forceinline__ void unpack2(unsigned long long p, float& lo, float& hi) {
    asm("mov.b64 {%0, %1}, %2;" : "=f"(lo), "=f"(hi) : "l"(p));
}

// ---------------- kernel 0: zero accumulators --------------------------------
__global__ void k_zero() {
    int i = blockIdx.x*blockDim.x + threadIdx.x;
    if (i < BB*NV*FF) { g_lhs[i] = 0.f; g_R2[i] = 0.f; }
}

// ---------------- kernel 1: streaming reductions over T -----------------------
__global__ void __launch_bounds__(256) k1_reduce(
    const float* __restrict__ x, const float* __restrict__ W1,
    const float* __restrict__ W2, const float* __restrict__ W3)
{
    const int b  = blockIdx.y;
    const int t0 = blockIdx.x * 128;
    const int j  = threadIdx.x;
    const int n  = j >> 2;
    const int f0 = (j & 3) * 4;

    __shared__ __align__(16) float sW1[128];
    __shared__ __align__(16) float sW2[16][129];

    if (j < 128) sW1[j] = W1[t0 + j];
    for (int idx = j; idx < 16*128; idx += 256) {
        int f = idx >> 7, tt = idx & 127;
        sW2[f][tt] = W2[f*TT + t0 + tt];
    }
    float w3v[4];
    #pragma unroll
    for (int d = 0; d < 4; d++) w3v[d] = W3[f0 + d];
    __syncthreads();

    float lhsacc[4] = {0,0,0,0};
    float r2acc[4]  = {0,0,0,0};
    const float4* xr = reinterpret_cast<const float4*>(
        x + (size_t)b*TT*CC + (size_t)t0*CC) + j;

    for (int tt = 0; tt < 128; tt++) {
        float4 xv = xr[(size_t)tt*256];
        float s3 = xv.x*w3v[0] + xv.y*w3v[1] + xv.z*w3v[2] + xv.w*w3v[3];
        s3 += __shfl_xor_sync(0xffffffffu, s3, 1);
        s3 += __shfl_xor_sync(0xffffffffu, s3, 2);
        float w1 = sW1[tt];
        lhsacc[0] += w1*xv.x; lhsacc[1] += w1*xv.y;
        lhsacc[2] += w1*xv.z; lhsacc[3] += w1*xv.w;
        #pragma unroll
        for (int d = 0; d < 4; d++) r2acc[d] += sW2[f0+d][tt] * s3;
    }
    #pragma unroll
    for (int d = 0; d < 4; d++) {
        atomicAdd(&g_lhs[(b*NV + n)*FF + f0 + d], lhsacc[d]);
        atomicAdd(&g_R2 [(b*NV + n)*FF + f0 + d], r2acc[d]);
    }
}

// ---------------- kernel 2a: attention matrix S -------------------------------
__global__ void __launch_bounds__(256) k2a_S(
    const float* __restrict__ bs, const float* __restrict__ Vs)
{
    const int b = blockIdx.x;
    const int tid = threadIdx.x;
    __shared__ __align__(16) float lhs_s[NV*FF];
    __shared__ __align__(16) float R2_s [NV*FF];
    __shared__ __align__(16) float P_s  [NV*NV];
    __shared__ __align__(16) float S0_s [NV*NV];

    for (int i = tid; i < NV*FF; i += 256) {
        lhs_s[i] = g_lhs[b*NV*FF + i];
        R2_s[i]  = g_R2 [b*NV*FF + i];
    }
    __syncthreads();

    for (int i = tid; i < NV*NV; i += 256) {
        int m = i >> 6, k = i & 63;
        float acc = 0.f;
        #pragma unroll
        for (int f = 0; f < FF; f++) acc += lhs_s[m*FF+f] * R2_s[k*FF+f];
        acc += bs[i];
        P_s[i] = 1.f / (1.f + expf(-acc));
    }
    __syncthreads();

    for (int i = tid; i < NV*NV; i += 256) {
        int nn = i >> 6, k = i & 63;
        float acc = 0.f;
        #pragma unroll 8
        for (int m = 0; m < NV; m++) acc += Vs[nn*NV+m] * P_s[m*NV+k];
        S0_s[i] = acc;
    }
    __syncthreads();

    if (tid < NV) {
        const int k = tid;
        float mx = -1e30f;
        for (int nn = 0; nn < NV; nn++) mx = fmaxf(mx, S0_s[nn*NV+k]);
        float sum = 0.f;
        for (int nn = 0; nn < NV; nn++) sum += expf(S0_s[nn*NV+k] - mx);
        float inv = 1.f / sum;
        for (int nn = 0; nn < NV; nn++)
            g_S[b*NV*NV + nn*NV + k] = expf(S0_s[nn*NV+k] - mx) * inv;
    }
}

// ---------------- kernel 2b: effective conv weights ---------------------------
// grid (O, B), block 256.
// Weff[b,o,m*F+f,k] = sum_n S[b,m,n]*adj[n,n]*conv_w[o,n*F+f,k]
// smem transpose cwT[f*3+k][nn] (pad 68 -> 16B aligned rows, conflict-free),
// vectorized float4 reduction over nn.
#define CWP 68
__global__ void __launch_bounds__(256) k2b_weff(
    const float* __restrict__ adj, const float* __restrict__ conv_w)
{
    const int o = blockIdx.x, b = blockIdx.y;
    const int tid = threadIdx.x;
    __shared__ __align__(16) float Sd[NV*NV];        // [m][nn]: S[b,m,nn]*dadj[nn]
    __shared__ __align__(16) float cwT[48*CWP];      // [f*3+k][nn]

    for (int i = tid; i < NV*NV; i += 256) {
        int nn = i & 63;
        Sd[i] = g_S[b*NV*NV + i] * adj[nn*NV + nn];
    }
    for (int i = tid; i < CC*3; i += 256) {
        int nn = i / 48, r = i - nn*48;      // i = nn*48 + (f*3+k)
        cwT[r*CWP + nn] = conv_w[(size_t)o*CC*3 + i];
    }
    __syncthreads();

    for (int i = tid; i < CC*3; i += 256) {
        int c = i / 3, k = i - c*3;
        int m = c >> 4, f = c & 15;
        const float4* srow = reinterpret_cast<const float4*>(&Sd[m*NV]);
        const float4* crow = reinterpret_cast<const float4*>(&cwT[(f*3+k)*CWP]);
        float acc = 0.f;
        #pragma unroll
        for (int q = 0; q < NV/4; q++) {
            float4 s = srow[q];
            float4 w = crow[q];
            acc += s.x*w.x + s.y*w.y + s.z*w.z + s.w*w.w;
        }
        g_Weff[(((size_t)b*3 + k)*CC + c)*OO + o] = acc;
    }
}

// ---------------- kernel 3: conv1d(x, Weff_b) ---------------------------------
// out[b,t,o] = sum_k sum_c x[b,t+k-1,c] * Weff[b,k,c,o]
// grid (T/128, B), block 128. Thread (tx,ty): 8t x 4o tile, f32x2 packed FMA.
// Software-pipelined: prefetch next chunk's gmem tiles into regs during compute.
#define K3TT 128
#define K3CH 32
#define XS_STRIDE 33
#define XS_F4 ((K3TT+2)*(K3CH/4))   // 1040 float4 per chunk
#define WS_F4 (3*K3CH*OO/4)         // 768 float4 per chunk

__global__ void __launch_bounds__(128) k3_conv(
    const float* __restrict__ x, float* __restrict__ out)
{
    const int b    = blockIdx.y;
    const int tblk = blockIdx.x * K3TT;
    const int tid  = threadIdx.x;
    const int tx   = tid & 7;    // o = 4*tx .. 4*tx+3
    const int ty   = tid >> 3;   // t rows ty*8 .. ty*8+7

    __shared__ __align__(16) float xs[(K3TT+2)*XS_STRIDE];
    __shared__ __align__(16) float ws[3*K3CH*OO];

    unsigned long long accp[8][2];
    const unsigned long long z2 = splat2(0.f);
    #pragma unroll
    for (int r = 0; r < 8; r++) { accp[r][0] = z2; accp[r][1] = z2; }

    const float* xb = x + (size_t)b*TT*CC;
    const float* wb = g_Weff + (size_t)b*3*CC*OO;

    float4 xpre[9];
    float4 wpre[6];

    // ---- prefetch chunk 0 ----
    {
        const int c0 = 0;
        #pragma unroll
        for (int i = 0; i < 9; i++) {
            int idx = tid + i*128;
            if (idx < XS_F4) {
                int row = idx >> 3, q = idx & 7;
                int tg = tblk - 1 + row;
                float4 v = make_float4(0.f,0.f,0.f,0.f);
                if (tg >= 0 && tg < TT)
                    v = *reinterpret_cast<const float4*>(xb + (size_t)tg*CC + c0 + q*4);
                xpre[i] = v;
            }
        }
        #pragma unroll
        for (int i = 0; i < 6; i++) {
            int e = (tid + i*128) * 4;
            int k = e / (K3CH*OO);
            int rem = e - k*K3CH*OO;
            wpre[i] = *reinterpret_cast<const float4*>(
                wb + (size_t)k*CC*OO + (size_t)c0*OO + rem);
        }
    }

    for (int ch = 0; ch < CC/K3CH; ch++) {
        __syncthreads();   // previous compute done reading smem
        // ---- store prefetched regs -> smem ----
        #pragma unroll
        for (int i = 0; i < 9; i++) {
            int idx = tid + i*128;
            if (idx < XS_F4) {
                int row = idx >> 3, q = idx & 7;
                float* dst = &xs[row*XS_STRIDE + q*4];
                dst[0]=xpre[i].x; dst[1]=xpre[i].y; dst[2]=xpre[i].z; dst[3]=xpre[i].w;
            }
        }
        #pragma unroll
        for (int i = 0; i < 6; i++)
            *reinterpret_cast<float4*>(ws + (tid + i*128)*4) = wpre[i];
        __syncthreads();   // smem visible

        // ---- prefetch chunk ch+1 (hidden under compute) ----
        if (ch + 1 < CC/K3CH) {
            const int c0 = (ch+1) * K3CH;
            #pragma unroll
            for (int i = 0; i < 9; i++) {
                int idx = tid + i*128;
                if (idx < XS_F4) {
                    int row = idx >> 3, q = idx & 7;
                    int tg = tblk - 1 + row;
                    float4 v = make_float4(0.f,0.f,0.f,0.f);
                    if (tg >= 0 && tg < TT)
                        v = *reinterpret_cast<const float4*>(xb + (size_t)tg*CC + c0 + q*4);
                    xpre[i] = v;
                }
            }
            #pragma unroll
            for (int i = 0; i < 6; i++) {
                int e = (tid + i*128) * 4;
                int k = e / (K3CH*OO);
                int rem = e - k*K3CH*OO;
                wpre[i] = *reinterpret_cast<const float4*>(
                    wb + (size_t)k*CC*OO + (size_t)c0*OO + rem);
            }
        }

        // ---- compute chunk ch ----
        for (int cc = 0; cc < K3CH; cc++) {
            unsigned long long xvp[10];
            #pragma unroll
            for (int rr = 0; rr < 10; rr++)
                xvp[rr] = splat2(xs[(ty*8 + rr)*XS_STRIDE + cc]);
            // each ulonglong2 = two packed (o,o+1) weight pairs
            ulonglong2 w0 = *reinterpret_cast<const ulonglong2*>(ws + (0*K3CH+cc)*OO + tx*4);
            ulonglong2 w1 = *reinterpret_cast<const ulonglong2*>(ws + (1*K3CH+cc)*OO + tx*4);
            ulonglong2 w2 = *reinterpret_cast<const ulonglong2*>(ws + (2*K3CH+cc)*OO + tx*4);
            #pragma unroll
            for (int r = 0; r < 8; r++) {
                ffma2(accp[r][0], xvp[r],   w0.x);
                ffma2(accp[r][1], xvp[r],   w0.y);
                ffma2(accp[r][0], xvp[r+1], w1.x);
                ffma2(accp[r][1], xvp[r+1], w1.y);
                ffma2(accp[r][0], xvp[r+2], w2.x);
                ffma2(accp[r][1], xvp[r+2], w2.y);
            }
        }
    }

    float* ob = out + (size_t)b*TT*OO;
    #pragma unroll
    for (int r = 0; r < 8; r++) {
        int t = tblk + ty*8 + r;
        float4 v;
        unpack2(accp[r][0], v.x, v.y);
        unpack2(accp[r][1], v.z, v.w);
        *reinterpret_cast<float4*>(ob + (size_t)t*OO + tx*4) = v;
    }
}

// ---------------- launch ------------------------------------------------------
extern "C" void kernel_launch(void* const* d_in, const int* in_sizes, int n_in,
                              void* d_out, int out_size)
{
    const float* x      = (const float*)d_in[0];
    const float* adj    = (const float*)d_in[1];
    const float* W1     = (const float*)d_in[2];
    const float* W2     = (const float*)d_in[3];
    const float* W3     = (const float*)d_in[4];
    const float* bs     = (const float*)d_in[5];
    const float* Vs     = (const float*)d_in[6];
    const float* conv_w = (const float*)d_in[7];
    float* out = (float*)d_out;

    k_zero<<<16, 256>>>();
    k1_reduce<<<dim3(TT/128, BB), 256>>>(x, W1, W2, W3);
    k2a_S<<<BB, 256>>>(bs, Vs);
    k2b_weff<<<dim3(OO, BB), 256>>>(adj, conv_w);
    k3_conv<<<dim3(TT/K3TT, BB), 128>>>(x, out);
}

// round 6
// speedup vs baseline: 2.4792x; 2.2608x over previous
#include <cuda_runtime.h>
#include <math.h>
#include <stdint.h>

#define BB 4
#define TT 8192
#define NV 64
#define FF 16
#define CC 1024   // NV*FF
#define OO 32
#define NCAT 96   // 3 taps * 32 outputs

// ---------------- scratch (static device globals; no allocation) -------------
__device__ __align__(16) float g_lhs[BB*NV*FF];
__device__ __align__(16) float g_R2 [BB*NV*FF];
__device__ __align__(16) float g_S  [BB*NV*NV];
__device__ __align__(16) float g_WT [BB*NCAT*CC];         // WT[b][oc][c], tf32-rounded
__device__ __align__(16) float g_G  [(size_t)BB*TT*NCAT]; // G[b][t][oc]

// ---------------- helpers -----------------------------------------------------
__device__ __forceinline__ uint32_t smem_u32(const void* p) {
    uint32_t a;
    asm("{ .reg .u64 t; cvta.to.shared.u64 t, %1; cvt.u32.u64 %0, t; }"
        : "=r"(a) : "l"(p));
    return a;
}
__device__ __forceinline__ void cp16(uint32_t dst, const void* src) {
    asm volatile("cp.async.cg.shared.global [%0], [%1], 16;"
                 :: "r"(dst), "l"(src) : "memory");
}
__device__ __forceinline__ void cp_commit() {
    asm volatile("cp.async.commit_group;" ::: "memory");
}
template<int N> __device__ __forceinline__ void cp_wait() {
    asm volatile("cp.async.wait_group %0;" :: "n"(N) : "memory");
}
__device__ __forceinline__ uint32_t f2tf32(float f) {
    uint32_t u;
    asm("cvt.rna.tf32.f32 %0, %1;" : "=r"(u) : "f"(f));
    return u;
}
__device__ __forceinline__ void mma_tf32(float* d, const uint32_t* a,
                                         const uint32_t* bfr) {
    asm volatile(
        "mma.sync.aligned.m16n8k8.row.col.f32.tf32.tf32.f32 "
        "{%0,%1,%2,%3}, {%4,%5,%6,%7}, {%8,%9}, {%0,%1,%2,%3};"
        : "+f"(d[0]), "+f"(d[1]), "+f"(d[2]), "+f"(d[3])
        : "r"(a[0]), "r"(a[1]), "r"(a[2]), "r"(a[3]),
          "r"(bfr[0]), "r"(bfr[1]));
}

// ---------------- kernel 0: zero accumulators --------------------------------
__global__ void k_zero() {
    int i = blockIdx.x*blockDim.x + threadIdx.x;
    if (i < BB*NV*FF) { g_lhs[i] = 0.f; g_R2[i] = 0.f; }
}

// ---------------- kernel 1: streaming reductions over T -----------------------
__global__ void __launch_bounds__(256) k1_reduce(
    const float* __restrict__ x, const float* __restrict__ W1,
    const float* __restrict__ W2, const float* __restrict__ W3)
{
    const int b  = blockIdx.y;
    const int t0 = blockIdx.x * 128;
    const int j  = threadIdx.x;
    const int n  = j >> 2;
    const int f0 = (j & 3) * 4;

    __shared__ __align__(16) float sW1[128];
    __shared__ __align__(16) float sW2[16][129];

    if (j < 128) sW1[j] = W1[t0 + j];
    for (int idx = j; idx < 16*128; idx += 256) {
        int f = idx >> 7, tt = idx & 127;
        sW2[f][tt] = W2[f*TT + t0 + tt];
    }
    float w3v[4];
    #pragma unroll
    for (int d = 0; d < 4; d++) w3v[d] = W3[f0 + d];
    __syncthreads();

    float lhsacc[4] = {0,0,0,0};
    float r2acc[4]  = {0,0,0,0};
    const float4* xr = reinterpret_cast<const float4*>(
        x + (size_t)b*TT*CC + (size_t)t0*CC) + j;

    for (int tt = 0; tt < 128; tt++) {
        float4 xv = xr[(size_t)tt*256];
        float s3 = xv.x*w3v[0] + xv.y*w3v[1] + xv.z*w3v[2] + xv.w*w3v[3];
        s3 += __shfl_xor_sync(0xffffffffu, s3, 1);
        s3 += __shfl_xor_sync(0xffffffffu, s3, 2);
        float w1 = sW1[tt];
        lhsacc[0] += w1*xv.x; lhsacc[1] += w1*xv.y;
        lhsacc[2] += w1*xv.z; lhsacc[3] += w1*xv.w;
        #pragma unroll
        for (int d = 0; d < 4; d++) r2acc[d] += sW2[f0+d][tt] * s3;
    }
    #pragma unroll
    for (int d = 0; d < 4; d++) {
        atomicAdd(&g_lhs[(b*NV + n)*FF + f0 + d], lhsacc[d]);
        atomicAdd(&g_R2 [(b*NV + n)*FF + f0 + d], r2acc[d]);
    }
}

// ---------------- kernel 2a: attention matrix S -------------------------------
__global__ void __launch_bounds__(256) k2a_S(
    const float* __restrict__ bs, const float* __restrict__ Vs)
{
    const int b = blockIdx.x;
    const int tid = threadIdx.x;
    __shared__ __align__(16) float lhs_s[NV*FF];
    __shared__ __align__(16) float R2_s [NV*FF];
    __shared__ __align__(16) float P_s  [NV*NV];
    __shared__ __align__(16) float S0_s [NV*NV];

    for (int i = tid; i < NV*FF; i += 256) {
        lhs_s[i] = g_lhs[b*NV*FF + i];
        R2_s[i]  = g_R2 [b*NV*FF + i];
    }
    __syncthreads();

    for (int i = tid; i < NV*NV; i += 256) {
        int m = i >> 6, k = i & 63;
        float acc = 0.f;
        #pragma unroll
        for (int f = 0; f < FF; f++) acc += lhs_s[m*FF+f] * R2_s[k*FF+f];
        acc += bs[i];
        P_s[i] = 1.f / (1.f + expf(-acc));
    }
    __syncthreads();

    for (int i = tid; i < NV*NV; i += 256) {
        int nn = i >> 6, k = i & 63;
        float acc = 0.f;
        #pragma unroll 8
        for (int m = 0; m < NV; m++) acc += Vs[nn*NV+m] * P_s[m*NV+k];
        S0_s[i] = acc;
    }
    __syncthreads();

    if (tid < NV) {
        const int k = tid;
        float mx = -1e30f;
        for (int nn = 0; nn < NV; nn++) mx = fmaxf(mx, S0_s[nn*NV+k]);
        float sum = 0.f;
        for (int nn = 0; nn < NV; nn++) sum += expf(S0_s[nn*NV+k] - mx);
        float inv = 1.f / sum;
        for (int nn = 0; nn < NV; nn++)
            g_S[b*NV*NV + nn*NV + k] = expf(S0_s[nn*NV+k] - mx) * inv;
    }
}

// ---------------- kernel 2b: WT[b][k*32+o][m*16+f], tf32-rounded ---------------
__global__ void __launch_bounds__(256) k2b_wt(
    const float* __restrict__ adj, const float* __restrict__ conv_w)
{
    const int oc = blockIdx.x, b = blockIdx.y;
    const int k = oc >> 5, o = oc & 31;
    const int tid = threadIdx.x;
    __shared__ __align__(16) float Sd[NV*NV];     // [m][n]
    __shared__ __align__(16) float cwk[CC];       // [n*16+f]

    for (int i = tid; i < NV*NV; i += 256) {
        int nn = i & 63;
        Sd[i] = g_S[b*NV*NV + i] * adj[nn*NV + nn];
    }
    for (int i = tid; i < CC; i += 256)
        cwk[i] = conv_w[(size_t)o*CC*3 + i*3 + k];
    __syncthreads();

    #pragma unroll
    for (int j = 0; j < 4; j++) {
        int c = tid*4 + j;
        int m = c >> 4, f = c & 15;
        float a0 = 0.f, a1 = 0.f;
        #pragma unroll 8
        for (int nn = 0; nn < NV; nn += 2) {
            a0 += Sd[m*NV+nn]   * cwk[nn*FF+f];
            a1 += Sd[m*NV+nn+1] * cwk[(nn+1)*FF+f];
        }
        g_WT[((size_t)b*NCAT + oc)*CC + c] = __uint_as_float(f2tf32(a0 + a1));
    }
}

// ---------------- kernel 3: G = x @ WT^T via mma.sync tf32 --------------------
// grid (TT/128, BB), 128 threads (4 warps). Warp: 32 rows x 96 cols.
// K staged in 32-float chunks, double-buffered cp.async, pad-36 smem rows.
#define MT   128
#define KC   32
#define NSTG (CC/KC)          // 32
#define ROWP 36               // floats per smem row (conflict-free)
#define XOFF0 0
#define WOFF0 (MT*ROWP*4)                 // 18432 B
#define XOFF1 (WOFF0 + NCAT*ROWP*4)       // 32256 B
#define WOFF1 (XOFF1 + MT*ROWP*4)         // 50688 B
#define SMEM_K3 (WOFF1 + NCAT*ROWP*4)     // 64512 B

__global__ void __launch_bounds__(128) k3_mma(const float* __restrict__ x)
{
    extern __shared__ __align__(16) float smemf[];
    const uint32_t sb = smem_u32(smemf);
    const int tid  = threadIdx.x;
    const int wid  = tid >> 5, lane = tid & 31;
    const int g    = lane >> 2;           // group id 0..7
    const int t4   = lane & 3;            // 0..3
    const int b    = blockIdx.y;
    const size_t m0 = (size_t)blockIdx.x * MT;

    const char* xg = (const char*)(x + ((size_t)b*TT + m0)*CC);
    const char* wg = (const char*)(g_WT + (size_t)b*NCAT*CC);

    float acc[2][12][4];
    #pragma unroll
    for (int mi = 0; mi < 2; mi++)
        #pragma unroll
        for (int j = 0; j < 12; j++)
            #pragma unroll
            for (int d = 0; d < 4; d++) acc[mi][j][d] = 0.f;

    // stage loader: 128 x-rows (8 cp/thread) + 96 w-rows (6 cp/thread)
    #define LOAD_STAGE(s) do {                                                  \
        uint32_t xd = sb + (((s)&1) ? XOFF1 : XOFF0);                           \
        uint32_t wd = sb + (((s)&1) ? WOFF1 : WOFF0);                           \
        int c0b = (s)*KC*4;                                                     \
        _Pragma("unroll")                                                       \
        for (int i = 0; i < 8; i++) {                                           \
            int idx = tid + i*128; int row = idx >> 3, q = idx & 7;             \
            cp16(xd + row*(ROWP*4) + q*16, xg + (size_t)row*CC*4 + c0b + q*16); \
        }                                                                       \
        _Pragma("unroll")                                                       \
        for (int i = 0; i < 6; i++) {                                           \
            int idx = tid + i*128; int row = idx >> 3, q = idx & 7;             \
            cp16(wd + row*(ROWP*4) + q*16, wg + (size_t)row*CC*4 + c0b + q*16); \
        }                                                                       \
        cp_commit();                                                            \
    } while (0)

    LOAD_STAGE(0);

    for (int s = 0; s < NSTG; s++) {
        if (s + 1 < NSTG) { LOAD_STAGE(s + 1); cp_wait<1>(); }
        else              { cp_wait<0>(); }
        __syncthreads();

        const float* xs = smemf + (((s&1) ? XOFF1 : XOFF0) >> 2);
        const float* ws = smemf + (((s&1) ? WOFF1 : WOFF0) >> 2);
        const int wr = wid * 32;

        #pragma unroll
        for (int ks = 0; ks < 4; ks++) {
            const int k0 = ks * 8;
            uint32_t afr[2][4];
            #pragma unroll
            for (int mi = 0; mi < 2; mi++) {
                int r0 = wr + mi*16 + g;
                afr[mi][0] = f2tf32(xs[(r0    )*ROWP + k0 + t4    ]);
                afr[mi][1] = f2tf32(xs[(r0 + 8)*ROWP + k0 + t4    ]);
                afr[mi][2] = f2tf32(xs[(r0    )*ROWP + k0 + t4 + 4]);
                afr[mi][3] = f2tf32(xs[(r0 + 8)*ROWP + k0 + t4 + 4]);
            }
            uint32_t bfr[12][2];
            #pragma unroll
            for (int j = 0; j < 12; j++) {
                int nr = 8*j + g;
                bfr[j][0] = __float_as_uint(ws[nr*ROWP + k0 + t4    ]);
                bfr[j][1] = __float_as_uint(ws[nr*ROWP + k0 + t4 + 4]);
            }
            #pragma unroll
            for (int mi = 0; mi < 2; mi++)
                #pragma unroll
                for (int j = 0; j < 12; j++)
                    mma_tf32(acc[mi][j], afr[mi], bfr[j]);
        }
        __syncthreads();
    }

    // epilogue: C frag (row g / g+8, cols 2*t4, 2*t4+1) per 16x8 tile
    float* gr = g_G + ((size_t)b*TT + m0 + (size_t)wid*32)*NCAT;
    #pragma unroll
    for (int mi = 0; mi < 2; mi++) {
        #pragma unroll
        for (int j = 0; j < 12; j++) {
            int col = 8*j + 2*t4;
            int r0 = mi*16 + g;
            *reinterpret_cast<float2*>(gr + (size_t)r0*NCAT + col) =
                make_float2(acc[mi][j][0], acc[mi][j][1]);
            *reinterpret_cast<float2*>(gr + (size_t)(r0+8)*NCAT + col) =
                make_float2(acc[mi][j][2], acc[mi][j][3]);
        }
    }
}

// ---------------- kernel 4: out[t,o] = G[t-1,o] + G[t,32+o] + G[t+1,64+o] -----
__global__ void __launch_bounds__(256) k4_combine(float* __restrict__ out)
{
    const int b = blockIdx.y;
    const int idx = blockIdx.x*256 + threadIdx.x;   // over TT*8
    const int t = idx >> 3, q = idx & 7;
    const float* Gb = g_G + (size_t)b*TT*NCAT;

    float4 acc = make_float4(0.f, 0.f, 0.f, 0.f);
    if (t > 0) {
        float4 v = *reinterpret_cast<const float4*>(Gb + (size_t)(t-1)*NCAT + q*4);
        acc.x += v.x; acc.y += v.y; acc.z += v.z; acc.w += v.w;
    }
    {
        float4 v = *reinterpret_cast<const float4*>(Gb + (size_t)t*NCAT + 32 + q*4);
        acc.x += v.x; acc.y += v.y; acc.z += v.z; acc.w += v.w;
    }
    if (t < TT-1) {
        float4 v = *reinterpret_cast<const float4*>(Gb + (size_t)(t+1)*NCAT + 64 + q*4);
        acc.x += v.x; acc.y += v.y; acc.z += v.z; acc.w += v.w;
    }
    *reinterpret_cast<float4*>(out + ((size_t)b*TT + t)*OO + q*4) = acc;
}

// ---------------- launch ------------------------------------------------------
extern "C" void kernel_launch(void* const* d_in, const int* in_sizes, int n_in,
                              void* d_out, int out_size)
{
    const float* x      = (const float*)d_in[0];
    const float* adj    = (const float*)d_in[1];
    const float* W1     = (const float*)d_in[2];
    const float* W2     = (const float*)d_in[3];
    const float* W3     = (const float*)d_in[4];
    const float* bs     = (const float*)d_in[5];
    const float* Vs     = (const float*)d_in[6];
    const float* conv_w = (const float*)d_in[7];
    float* out = (float*)d_out;

    cudaFuncSetAttribute(k3_mma, cudaFuncAttributeMaxDynamicSharedMemorySize,
                         SMEM_K3);

    k_zero<<<16, 256>>>();
    k1_reduce<<<dim3(TT/128, BB), 256>>>(x, W1, W2, W3);
    k2a_S<<<BB, 256>>>(bs, Vs);
    k2b_wt<<<dim3(NCAT, BB), 256>>>(adj, conv_w);
    k3_mma<<<dim3(TT/MT, BB), 128, SMEM_K3>>>(x);
    k4_combine<<<dim3(TT*8/256, BB), 256>>>(out);
}